// round 12
// baseline (speedup 1.0000x reference)
#include <cuda_runtime.h>

#define NPRIMES 168
#define TPB 512            // 16 warps: 12 gather + 4 stream
#define GW  12             // gather warps per block
#define COLS 512           // columns per block
#define CHUNK 32           // columns per gather unit / stream unit
#define NCHUNK (COLS / CHUNK)   // 16
#define TABN (NPRIMES * 1000)

// Interleaved (kernel, bias) table: one LDG.64 fetches both values.
__device__ float2 g_tab[TABN];

// Per-prime magic-mod descriptor (compile-time, constant memory):
//  magic = floor(2^32/p)+1  ->  k % p == k - p*umulhi(k, magic)   (k < 2^20)
struct PInfo { unsigned magic; int p; };

#define PRIME_LIST \
 X(2) X(3) X(5) X(7) X(11) X(13) X(17) X(19) X(23) X(29) \
 X(31) X(37) X(41) X(43) X(47) X(53) X(59) X(61) X(67) X(71) \
 X(73) X(79) X(83) X(89) X(97) X(101) X(103) X(107) X(109) X(113) \
 X(127) X(131) X(137) X(139) X(149) X(151) X(157) X(163) X(167) X(173) \
 X(179) X(181) X(191) X(193) X(197) X(199) X(211) X(223) X(227) X(229) \
 X(233) X(239) X(241) X(251) X(257) X(263) X(269) X(271) X(277) X(281) \
 X(283) X(293) X(307) X(311) X(313) X(317) X(331) X(337) X(347) X(349) \
 X(353) X(359) X(367) X(373) X(379) X(383) X(389) X(397) X(401) X(409) \
 X(419) X(421) X(431) X(433) X(439) X(443) X(449) X(457) X(461) X(463) \
 X(467) X(479) X(487) X(491) X(499) X(503) X(509) X(521) X(523) X(541) \
 X(547) X(557) X(563) X(569) X(571) X(577) X(587) X(593) X(599) X(601) \
 X(607) X(613) X(617) X(619) X(631) X(641) X(643) X(647) X(653) X(659) \
 X(661) X(673) X(677) X(683) X(691) X(701) X(709) X(719) X(727) X(733) \
 X(739) X(743) X(751) X(757) X(761) X(769) X(773) X(787) X(797) X(809) \
 X(811) X(821) X(823) X(827) X(829) X(839) X(853) X(857) X(859) X(863) \
 X(877) X(881) X(883) X(887) X(907) X(911) X(919) X(929) X(937) X(941) \
 X(947) X(953) X(967) X(971) X(977) X(983) X(991) X(997)

__constant__ PInfo C_PI[NPRIMES] = {
#define X(p) { 0xFFFFFFFFu / (unsigned)(p) + 1u, (p) },
  PRIME_LIST
#undef X
};

__global__ __launch_bounds__(256)
void interleave_tab(const float* __restrict__ kern, const float* __restrict__ bias)
{
    int i = blockIdx.x * 256 + threadIdx.x;
    if (i < TABN) g_tab[i] = make_float2(kern[i], bias[i]);
}

__global__ __launch_bounds__(TPB, 4)
void bwl_prime_main(const float* __restrict__ x,
                    float* __restrict__ out,
                    int N, int B)
{
    __shared__ float2 wb_s[COLS];      // (w,b) per column
    __shared__ int    flag[NCHUNK];    // per-chunk ready flags

    const int t    = threadIdx.x;
    const int wid  = t >> 5;
    const int lane = t & 31;
    const int base = blockIdx.x * COLS;
    const size_t nv = (size_t)(N >> 2);

    if (t < NCHUNK) flag[t] = 0;
    __syncthreads();

    if (wid < GW) {
        // ============ GATHER: warps 0-11 (48/SM keeps L1 at its 21us floor) ====
        // warp w: chunk w (round 1), then chunk w+GW if it exists (round 2).
#pragma unroll
        for (int rnd = 0; rnd < 2; ++rnd) {
            const int c = wid + rnd * GW;
            if (c >= NCHUNK) break;

            const unsigned k = (unsigned)(base + c * CHUNK + lane);
            float w = 0.f, a = 0.f;
            const float2* __restrict__ row = g_tab;

#pragma unroll 8
            for (int i = 0; i < NPRIMES; ++i) {
                const PInfo pi = C_PI[i];
                int m = (int)(k - (unsigned)pi.p * __umulhi(k, pi.magic)); // k%p
                float2 e = __ldg(row + m);
                w += e.x; a += e.y;
                row += 1000;
            }
            wb_s[c * CHUNK + lane] = make_float2(w, a);

            __syncwarp();
            if (lane == 0) {
                unsigned fa = (unsigned)__cvta_generic_to_shared(&flag[c]);
                asm volatile("st.release.cta.shared.b32 [%0], %1;"
                             :: "r"(fa), "r"(1) : "memory");
            }
        }
        // gather warps retire; stream warps keep the block alive
    } else {
        // ============ STREAM: warps 12-15 (16/SM saturate DRAM) ============
        const int s    = wid - GW;          // 0..3
        const int col4 = lane & 7;          // float4 column within chunk
        const int rpg  = B >> 2;            // 16 rows per group
        const int rbeg = (lane >> 3) * rpg; // 4 row-groups

        // stream warp s consumes chunks s, s+4, s+8, s+12
#pragma unroll
        for (int j = 0; j < NCHUNK / 4; ++j) {
            const int c = s + j * 4;

            // acquire-spin with sleep backoff (cheap: 4 warps/block only)
            {
                unsigned fa = (unsigned)__cvta_generic_to_shared(&flag[c]);
                int f;
                for (;;) {
                    asm volatile("ld.acquire.cta.shared.b32 %0, [%1];"
                                 : "=r"(f) : "r"(fa) : "memory");
                    if (f) break;
                    __nanosleep(128);
                }
            }

            const float2 q0 = wb_s[c * CHUNK + col4 * 4 + 0];
            const float2 q1 = wb_s[c * CHUNK + col4 * 4 + 1];
            const float2 q2 = wb_s[c * CHUNK + col4 * 4 + 2];
            const float2 q3 = wb_s[c * CHUNK + col4 * 4 + 3];

            const int k0 = base + c * CHUNK;
            const float4* __restrict__ xv = reinterpret_cast<const float4*>(x)
                                            + (size_t)rbeg * nv + (k0 >> 2) + col4;
            float4* __restrict__       ov = reinterpret_cast<float4*>(out)
                                            + (size_t)rbeg * nv + (k0 >> 2) + col4;

#pragma unroll 8
            for (int r = 0; r < rpg; ++r) {
                float4 xi = __ldcg(xv);     // L2-only: keep L1 for the gather
                float4 o;
                o.x = fmaf(xi.x, q0.x, q0.y);
                o.y = fmaf(xi.y, q1.x, q1.y);
                o.z = fmaf(xi.z, q2.x, q2.y);
                o.w = fmaf(xi.w, q3.x, q3.y);
                __stcg(ov, o);
                xv += nv;
                ov += nv;
            }
        }
    }
}

extern "C" void kernel_launch(void* const* d_in, const int* in_sizes, int n_in,
                              void* d_out, int out_size)
{
    const float* x  = (const float*)d_in[0];   // (B, N) float32
    const float* kr = (const float*)d_in[1];   // (168, 1000) float32
    const float* br = (const float*)d_in[2];   // (168, 1000) float32
    float* out = (float*)d_out;

    const int N = 524288;
    const int B = in_sizes[0] / N;             // 64

    interleave_tab<<<(TABN + 255) / 256, 256>>>(kr, br);

    const int grid = N / COLS;                 // 1024 blocks
    bwl_prime_main<<<grid, TPB>>>(x, out, N, B);
}

// round 13
// speedup vs baseline: 1.6465x; 1.6465x over previous
#include <cuda_runtime.h>

#define NPRIMES 168
#define TPB 128
#define COLS 128           // columns per tile
#define TABN (NPRIMES * 1000)

// Interleaved (kernel, bias) table: one LDG.64 fetches both values.
__device__ float2 g_tab[TABN];

// Per-prime magic-mod descriptor (compile-time, constant memory):
//  magic = floor(2^32/p)+1  ->  k % p == k - p*umulhi(k, magic)   (k < 2^20)
struct PInfo { unsigned magic; int p; };

#define PRIME_LIST \
 X(2) X(3) X(5) X(7) X(11) X(13) X(17) X(19) X(23) X(29) \
 X(31) X(37) X(41) X(43) X(47) X(53) X(59) X(61) X(67) X(71) \
 X(73) X(79) X(83) X(89) X(97) X(101) X(103) X(107) X(109) X(113) \
 X(127) X(131) X(137) X(139) X(149) X(151) X(157) X(163) X(167) X(173) \
 X(179) X(181) X(191) X(193) X(197) X(199) X(211) X(223) X(227) X(229) \
 X(233) X(239) X(241) X(251) X(257) X(263) X(269) X(271) X(277) X(281) \
 X(283) X(293) X(307) X(311) X(313) X(317) X(331) X(337) X(347) X(349) \
 X(353) X(359) X(367) X(373) X(379) X(383) X(389) X(397) X(401) X(409) \
 X(419) X(421) X(431) X(433) X(439) X(443) X(449) X(457) X(461) X(463) \
 X(467) X(479) X(487) X(491) X(499) X(503) X(509) X(521) X(523) X(541) \
 X(547) X(557) X(563) X(569) X(571) X(577) X(587) X(593) X(599) X(601) \
 X(607) X(613) X(617) X(619) X(631) X(641) X(643) X(647) X(653) X(659) \
 X(661) X(673) X(677) X(683) X(691) X(701) X(709) X(719) X(727) X(733) \
 X(739) X(743) X(751) X(757) X(761) X(769) X(773) X(787) X(797) X(809) \
 X(811) X(821) X(823) X(827) X(829) X(839) X(853) X(857) X(859) X(863) \
 X(877) X(881) X(883) X(887) X(907) X(911) X(919) X(929) X(937) X(941) \
 X(947) X(953) X(967) X(971) X(977) X(983) X(991) X(997)

__constant__ PInfo C_PI[NPRIMES] = {
#define X(p) { 0xFFFFFFFFu / (unsigned)(p) + 1u, (p) },
  PRIME_LIST
#undef X
};

__global__ __launch_bounds__(256)
void interleave_tab(const float* __restrict__ kern, const float* __restrict__ bias)
{
    int i = blockIdx.x * 256 + threadIdx.x;
    if (i < TABN) g_tab[i] = make_float2(kern[i], bias[i]);
}

// Clean, fat gather for one column (preserves MLP; identical to R7's loop).
__device__ __forceinline__ float2 gather_col(unsigned k)
{
    float w = 0.f, a = 0.f;
    const float2* __restrict__ row = g_tab;
#pragma unroll 8
    for (int i = 0; i < NPRIMES; ++i) {
        const PInfo pi = C_PI[i];
        int m = (int)(k - (unsigned)pi.p * __umulhi(k, pi.magic));   // k % p
        float2 e = __ldg(row + m);
        w += e.x; a += e.y;
        row += 1000;
    }
    return make_float2(w, a);
}

__global__ __launch_bounds__(TPB, 12)
void bwl_prime_main(const float* __restrict__ x,
                    float* __restrict__ out,
                    int N, int B)
{
    __shared__ float2 wb_s[COLS];

    const int t    = threadIdx.x;
    const int base = blockIdx.x * (2 * COLS);   // this block: 2 tiles x 128 cols
    const size_t nv = (size_t)(N >> 2);

    const int col4 = t & 31;                    // float4 column within tile
    const int rbeg = (t >> 5) * 16;             // 4 row-groups x 16 rows (B=64)

    // ---- gather tile 0 (clean) ----
    wb_s[t] = gather_col((unsigned)(base + t));
    __syncthreads();

    float2 q0 = wb_s[col4 * 4 + 0];
    float2 q1 = wb_s[col4 * 4 + 1];
    float2 q2 = wb_s[col4 * 4 + 2];
    float2 q3 = wb_s[col4 * 4 + 3];
    __syncthreads();                            // wb_s reusable after reads

    // ---- stream tile 0  ∥  gather tile 1 (coarse-chunk interleave) ----
    // 8 segments x [2 independent DRAM float4 loads -> 21 clean L1 gather
    // loads -> consume the float4s]. No guards, exact trip counts:
    // 168 = 8*21, 16 stream iters = 8*2.
    const float4* __restrict__ xv = reinterpret_cast<const float4*>(x)
                                    + (size_t)rbeg * nv + (base >> 2) + col4;
    float4* __restrict__       ov = reinterpret_cast<float4*>(out)
                                    + (size_t)rbeg * nv + (base >> 2) + col4;

    const unsigned k1 = (unsigned)(base + COLS + t);
    float w1 = 0.f, a1 = 0.f;
    const float2* __restrict__ row1 = g_tab;

#pragma unroll
    for (int seg = 0; seg < 8; ++seg) {
        // (1) issue the DRAM loads early
        float4 xi0 = __ldcs(xv);
        float4 xi1 = __ldcs(xv + nv);

        // (2) 21 gather loads fill the DRAM-latency window
#pragma unroll
        for (int j = 0; j < 21; ++j) {
            const PInfo pi = C_PI[seg * 21 + j];
            int m = (int)(k1 - (unsigned)pi.p * __umulhi(k1, pi.magic));
            float2 e = __ldg(row1 + m);
            w1 += e.x; a1 += e.y;
            row1 += 1000;
        }

        // (3) consume and store
        float4 o0, o1;
        o0.x = fmaf(xi0.x, q0.x, q0.y);
        o0.y = fmaf(xi0.y, q1.x, q1.y);
        o0.z = fmaf(xi0.z, q2.x, q2.y);
        o0.w = fmaf(xi0.w, q3.x, q3.y);
        o1.x = fmaf(xi1.x, q0.x, q0.y);
        o1.y = fmaf(xi1.y, q1.x, q1.y);
        o1.z = fmaf(xi1.z, q2.x, q2.y);
        o1.w = fmaf(xi1.w, q3.x, q3.y);
        __stcs(ov, o0);
        __stcs(ov + nv, o1);
        xv += 2 * nv;
        ov += 2 * nv;
    }

    // ---- publish tile-1 wb, then stream tile 1 (clean) ----
    wb_s[t] = make_float2(w1, a1);
    __syncthreads();

    q0 = wb_s[col4 * 4 + 0];
    q1 = wb_s[col4 * 4 + 1];
    q2 = wb_s[col4 * 4 + 2];
    q3 = wb_s[col4 * 4 + 3];

    const int k0b = base + COLS;
    const float4* __restrict__ xv2 = reinterpret_cast<const float4*>(x)
                                     + (size_t)rbeg * nv + (k0b >> 2) + col4;
    float4* __restrict__       ov2 = reinterpret_cast<float4*>(out)
                                     + (size_t)rbeg * nv + (k0b >> 2) + col4;

#pragma unroll 16
    for (int r = 0; r < 16; ++r) {
        float4 xi = __ldcs(xv2);
        float4 o;
        o.x = fmaf(xi.x, q0.x, q0.y);
        o.y = fmaf(xi.y, q1.x, q1.y);
        o.z = fmaf(xi.z, q2.x, q2.y);
        o.w = fmaf(xi.w, q3.x, q3.y);
        __stcs(ov2, o);
        xv2 += nv;
        ov2 += nv;
    }
}

extern "C" void kernel_launch(void* const* d_in, const int* in_sizes, int n_in,
                              void* d_out, int out_size)
{
    const float* x  = (const float*)d_in[0];   // (B, N) float32
    const float* kr = (const float*)d_in[1];   // (168, 1000) float32
    const float* br = (const float*)d_in[2];   // (168, 1000) float32
    float* out = (float*)d_out;

    const int N = 524288;
    const int B = in_sizes[0] / N;             // 64 (segment structure assumes 64)
    (void)B;

    interleave_tab<<<(TABN + 255) / 256, 256>>>(kr, br);

    const int grid = N / (2 * COLS);           // 2048 blocks, ~2 waves
    bwl_prime_main<<<grid, TPB>>>(x, out, N, 64);
}